// round 17
// baseline (speedup 1.0000x reference)
#include <cuda_runtime.h>
#include <cuda_bf16.h>
#include <cstdint>

// DLRM dot-interaction via BF16 tensor cores, 3-term split.
// One sample per 128-thread CTA. Load phase splits fp32 -> bf16 hi/lo PLANES
// (split off the hot loop). The 6 upper-triangle m16n8 tiles x k=128 are cut
// into 12 balanced jobs (tile, k-half): warp w = (h = w>>1, eg = w&1) computes
// tile-triple eg*3..eg*3+2 over k-half h. Pairwise reduction (w2->w0, w3->w1)
// through the dead plane smem. Every warp: 36 mmas — balanced critical path.
// A-fragments alias B-fragments (SYRK symmetry). 3 mmas/pos; dropped al*bl~2^-16.

constexpr int Bt    = 16384;
constexpr int NE    = 26;
constexpr int D     = 128;
constexpr int N     = 27;
constexpr int NPAIR = N * (N - 1) / 2;     // 351
constexpr int STRH  = 136;                 // shorts per plane row (272 B)
constexpr int NTHR  = 128;
constexpr int NF4   = 864;                 // float4 per sample (27 rows x 32)

__device__ __forceinline__ void mma_bf16(float* c,
    uint32_t a0, uint32_t a1, uint32_t a2, uint32_t a3,
    uint32_t b0, uint32_t b1)
{
    asm volatile(
        "mma.sync.aligned.m16n8k16.row.col.f32.bf16.bf16.f32 "
        "{%0,%1,%2,%3}, {%4,%5,%6,%7}, {%8,%9}, {%0,%1,%2,%3};"
        : "+f"(c[0]), "+f"(c[1]), "+f"(c[2]), "+f"(c[3])
        : "r"(a0), "r"(a1), "r"(a2), "r"(a3), "r"(b0), "r"(b1));
}

__global__ void __launch_bounds__(NTHR)
dot_interaction_kernel(const float* __restrict__ dense,
                       const float* __restrict__ embs,
                       float* __restrict__ out)
{
    __shared__ uint16_t Shi[32 * STRH];              // 8704 B
    __shared__ uint16_t Slo[32 * STRH];              // 8704 B

    const int tid  = threadIdx.x;
    const int w    = tid >> 5;
    const int lane = tid & 31;
    const int g    = lane >> 2;
    const int t4   = lane & 3;
    const int eg   = w & 1;                          // tile triple: 0 -> e0..2, 1 -> e3..5
    const int h    = w >> 1;                         // k-half
    const int sample = blockIdx.x;

    // ---- Load + split phase: fp32 gmem -> bf16 hi/lo planes ----
    const float4* d4 = reinterpret_cast<const float4*>(dense + (size_t)sample * D);
    const float4* e4 = reinterpret_cast<const float4*>(embs + (size_t)sample * NE * D);

    #pragma unroll
    for (int i = 0; i < 7; i++) {                    // 864 f4 over 128 threads
        const int idx = tid + i * NTHR;
        if (idx < NF4) {
            const int row = idx >> 5, c0 = (idx & 31) * 4;
            const float4 v = (idx < 32) ? d4[idx] : e4[idx - 32];
            const uint32_t bx = __float_as_uint(v.x), by = __float_as_uint(v.y);
            const uint32_t bz = __float_as_uint(v.z), bw = __float_as_uint(v.w);
            const uint32_t h0 = __byte_perm(bx, by, 0x7632);
            const uint32_t h1 = __byte_perm(bz, bw, 0x7632);
            __nv_bfloat162 l0 = __floats2bfloat162_rn(
                v.x - __uint_as_float(bx & 0xFFFF0000u),
                v.y - __uint_as_float(by & 0xFFFF0000u));
            __nv_bfloat162 l1 = __floats2bfloat162_rn(
                v.z - __uint_as_float(bz & 0xFFFF0000u),
                v.w - __uint_as_float(bw & 0xFFFF0000u));
            *reinterpret_cast<uint2*>(&Shi[row * STRH + c0]) = make_uint2(h0, h1);
            *reinterpret_cast<uint2*>(&Slo[row * STRH + c0]) =
                make_uint2(*reinterpret_cast<uint32_t*>(&l0),
                           *reinterpret_cast<uint32_t*>(&l1));
        }
    }
    for (int i = tid; i < 5 * (STRH / 2); i += NTHR) {   // zero pad rows 27..31
        reinterpret_cast<uint32_t*>(&Shi[27 * STRH])[i] = 0u;
        reinterpret_cast<uint32_t*>(&Slo[27 * STRH])[i] = 0u;
    }
    __syncthreads();

    // ---- Compute: 3 tiles over this warp's k-half (4 ktiles of 16) ----
    auto ldfrag = [&](int n, int kc, uint32_t* fh, uint32_t* fl) {
        fh[0] = *reinterpret_cast<const uint32_t*>(&Shi[n * STRH + kc    ]);
        fh[1] = *reinterpret_cast<const uint32_t*>(&Shi[n * STRH + kc + 8]);
        fl[0] = *reinterpret_cast<const uint32_t*>(&Slo[n * STRH + kc    ]);
        fl[1] = *reinterpret_cast<const uint32_t*>(&Slo[n * STRH + kc + 8]);
    };
    auto mma3 = [&](float* c, const uint32_t* hp, const uint32_t* hq,
                               const uint32_t* lp, const uint32_t* lq,
                               const uint32_t* bhn, const uint32_t* bln) {
        mma_bf16(c, lp[0], lq[0], lp[1], lq[1], bhn[0], bhn[1]);
        mma_bf16(c, hp[0], hq[0], hp[1], hq[1], bln[0], bln[1]);
        mma_bf16(c, hp[0], hq[0], hp[1], hq[1], bhn[0], bhn[1]);
    };

    float acc[3][4];
    #pragma unroll
    for (int q = 0; q < 3; q++)
        #pragma unroll
        for (int c = 0; c < 4; c++) acc[q][c] = 0.f;

    const int kbase = h * 64;
    if (eg == 0) {                                   // e0=(0,0) e1=(0,1) e2=(0,2)
        #pragma unroll
        for (int kt = 0; kt < 4; kt++) {
            const int kc = kbase + kt * 16 + 2 * t4;
            uint32_t h0[2], l0[2], h1[2], l1[2], h2[2], l2[2];
            ldfrag(g,      kc, h0, l0);
            ldfrag(8 + g,  kc, h1, l1);
            ldfrag(16 + g, kc, h2, l2);
            mma3(acc[0], h0, h1, l0, l1, h0, l0);    // B = b0
            mma3(acc[1], h0, h1, l0, l1, h1, l1);    // B = b1
            mma3(acc[2], h0, h1, l0, l1, h2, l2);    // B = b2
        }
    } else {                                         // e3=(0,3) e4=(1,2) e5=(1,3)
        #pragma unroll
        for (int kt = 0; kt < 4; kt++) {
            const int kc = kbase + kt * 16 + 2 * t4;
            uint32_t h0[2], l0[2], h1[2], l1[2], h2[2], l2[2], h3[2], l3[2];
            ldfrag(g,      kc, h0, l0);
            ldfrag(8 + g,  kc, h1, l1);
            ldfrag(16 + g, kc, h2, l2);
            ldfrag(24 + g, kc, h3, l3);
            mma3(acc[0], h0, h1, l0, l1, h3, l3);    // (0,3): A=(b0,b1), B=b3
            mma3(acc[1], h2, h3, l2, l3, h2, l2);    // (1,2): A=(b2,b3), B=b2
            mma3(acc[2], h2, h3, l2, l3, h3, l3);    // (1,3): A=(b2,b3), B=b3
        }
    }

    // ---- Pairwise reduction via dead plane smem (h=1 publishes, h=0 reduces) ----
    __syncthreads();                                 // all plane reads done
    float* Sf = reinterpret_cast<float*>(Shi);       // 768 floats needed, 8704 B avail
    if (h == 1) {
        #pragma unroll
        for (int q = 0; q < 3; q++)
            #pragma unroll
            for (int c = 0; c < 4; c++)
                Sf[((eg * 3 + q) * 4 + c) * 32 + lane] = acc[q][c];
    }
    __syncthreads();

    if (h == 0) {
        constexpr int MT[6] = {0, 0, 0, 0, 1, 1};
        constexpr int NT[6] = {0, 1, 2, 3, 2, 3};
        float* orow = out + (size_t)sample * NPAIR;
        #pragma unroll
        for (int q = 0; q < 3; q++) {
            const int e = eg * 3 + q;
            #pragma unroll
            for (int c = 0; c < 4; c++) {
                const float v = acc[q][c] + Sf[(e * 4 + c) * 32 + lane];
                const int i = MT[e] * 16 + g + ((c & 2) ? 8 : 0);
                const int j = NT[e] * 8 + 2 * t4 + (c & 1);
                if (i < j && j < N)
                    orow[i * (2 * N - 1 - i) / 2 + (j - i - 1)] = v;
            }
        }
    }
}

extern "C" void kernel_launch(void* const* d_in, const int* in_sizes, int n_in,
                              void* d_out, int out_size)
{
    const float* dense = (const float*)d_in[0];
    const float* embs  = (const float*)d_in[1];
    float* out = (float*)d_out;
    dot_interaction_kernel<<<Bt, NTHR>>>(dense, embs, out);
}